// round 4
// baseline (speedup 1.0000x reference)
#include <cuda_runtime.h>
#include <cuda_bf16.h>

#define HID 4096
#define MH 16384            // 4 * HIDDEN
#define TOK 4
#define NT 512
#define NWARP (NT / 32)
#define FS 1024             // float4 per stream (HID/4)
#define KH 2                // h-groups per thread (FS / NT)

__device__ __forceinline__ float bflo(unsigned u) {   // low bf16 -> f32
    return __uint_as_float(u << 16);
}
__device__ __forceinline__ float bfhi(unsigned u) {   // high bf16 -> f32
    return __uint_as_float(u & 0xFFFF0000u);
}

__global__ __launch_bounds__(NT, 1) void hchead_kernel(
    const float* __restrict__ x,
    const float* __restrict__ fn,
    const float* __restrict__ scale,
    const float* __restrict__ base,
    float* __restrict__ out)
{
    __shared__ float red[NWARP * 20];
    __shared__ float wsh[TOK * 4];

    const int tid  = threadIdx.x;
    const int warp = tid >> 5, lane = tid & 31;
    const size_t tok0 = (size_t)blockIdx.x * TOK;

    const float4* x4  = reinterpret_cast<const float4*>(x);
    const float4* fn4 = reinterpret_cast<const float4*>(fn);

    // Retained bf16-rounded x: [token][stream][h-group], 4 bf16 per uint2.
    uint2 xb[TOK][4][KH];

    // acc: t*5+0 = sum(x^2), t*5+1+mm = dot with fn[mm]
    float acc[20];
#pragma unroll
    for (int i = 0; i < 20; i++) acc[i] = 0.f;

    // ---------------- Phase 1: load / round / retain / accumulate ----------------
#pragma unroll
    for (int k = 0; k < KH; k++) {
        const int f = tid + k * NT;               // float4 index within a stream
#pragma unroll
        for (int m = 0; m < 4; m++) {             // stream (j = m*HID + 4f..)
            const int joff = m * FS + f;
            // fn rows 0..3 at this j-position
            float4 g0 = fn4[0 * (MH / 4) + joff];
            float4 g1 = fn4[1 * (MH / 4) + joff];
            float4 g2 = fn4[2 * (MH / 4) + joff];
            float4 g3 = fn4[3 * (MH / 4) + joff];
            // x for all 4 tokens at this j-position (independent loads -> MLP)
            float4 v0 = x4[(tok0 + 0) * (MH / 4) + joff];
            float4 v1 = x4[(tok0 + 1) * (MH / 4) + joff];
            float4 v2 = x4[(tok0 + 2) * (MH / 4) + joff];
            float4 v3 = x4[(tok0 + 3) * (MH / 4) + joff];
#pragma unroll
            for (int t = 0; t < TOK; t++) {
                float4 v = (t == 0) ? v0 : (t == 1) ? v1 : (t == 2) ? v2 : v3;
                __nv_bfloat162 b0 = __floats2bfloat162_rn(v.x, v.y);
                __nv_bfloat162 b1 = __floats2bfloat162_rn(v.z, v.w);
                uint2 st;
                st.x = *reinterpret_cast<unsigned*>(&b0);
                st.y = *reinterpret_cast<unsigned*>(&b1);
                xb[t][m][k] = st;
                const float x0 = bflo(st.x), x1 = bfhi(st.x);
                const float x2 = bflo(st.y), x3 = bfhi(st.y);
                acc[t * 5 + 0] += x0 * x0 + x1 * x1 + x2 * x2 + x3 * x3;
                acc[t * 5 + 1] += x0 * g0.x + x1 * g0.y + x2 * g0.z + x3 * g0.w;
                acc[t * 5 + 2] += x0 * g1.x + x1 * g1.y + x2 * g1.z + x3 * g1.w;
                acc[t * 5 + 3] += x0 * g2.x + x1 * g2.y + x2 * g2.z + x3 * g2.w;
                acc[t * 5 + 4] += x0 * g3.x + x1 * g3.y + x2 * g3.z + x3 * g3.w;
            }
        }
    }

    // ---------------- Block reduction of 20 partials ----------------
#pragma unroll
    for (int i = 0; i < 20; i++) {
#pragma unroll
        for (int o = 16; o > 0; o >>= 1)
            acc[i] += __shfl_xor_sync(0xffffffffu, acc[i], o);
    }
    if (lane == 0) {
#pragma unroll
        for (int i = 0; i < 20; i++) red[warp * 20 + i] = acc[i];
    }
    __syncthreads();

    if (tid < TOK) {
        const int t = tid;
        float ss = 0.f, d0 = 0.f, d1 = 0.f, d2 = 0.f, d3 = 0.f;
#pragma unroll
        for (int w = 0; w < NWARP; w++) {
            ss += red[w * 20 + t * 5 + 0];
            d0 += red[w * 20 + t * 5 + 1];
            d1 += red[w * 20 + t * 5 + 2];
            d2 += red[w * 20 + t * 5 + 3];
            d3 += red[w * 20 + t * 5 + 4];
        }
        const float inv = 1.0f / sqrtf(ss * (1.0f / MH) + 1e-6f);
        const float s = scale[0];
        const float a0 = s * (d0 * inv) + base[0];
        const float a1 = s * (d1 * inv) + base[1];
        const float a2 = s * (d2 * inv) + base[2];
        const float a3 = s * (d3 * inv) + base[3];
        const float idn = 1.0f / (fabsf(a0) + fabsf(a1) + fabsf(a2) + fabsf(a3) + 1e-6f);
        wsh[t * 4 + 0] = a0 * idn;
        wsh[t * 4 + 1] = a1 * idn;
        wsh[t * 4 + 2] = a2 * idn;
        wsh[t * 4 + 3] = a3 * idn;
    }
    __syncthreads();

    // ---------------- Phase 2: pure register combine + store ----------------
#pragma unroll
    for (int t = 0; t < TOK; t++) {
        const float w0 = wsh[t * 4 + 0], w1 = wsh[t * 4 + 1];
        const float w2 = wsh[t * 4 + 2], w3 = wsh[t * 4 + 3];
        float* op = out + (tok0 + t) * HID;
#pragma unroll
        for (int k = 0; k < KH; k++) {
            const int h0 = (tid + k * NT) * 4;
            uint2 s0 = xb[t][0][k], s1 = xb[t][1][k];
            uint2 s2 = xb[t][2][k], s3 = xb[t][3][k];
            float r0 = w0 * bflo(s0.x) + w1 * bflo(s1.x) + w2 * bflo(s2.x) + w3 * bflo(s3.x);
            float r1 = w0 * bfhi(s0.x) + w1 * bfhi(s1.x) + w2 * bfhi(s2.x) + w3 * bfhi(s3.x);
            float r2 = w0 * bflo(s0.y) + w1 * bflo(s1.y) + w2 * bflo(s2.y) + w3 * bflo(s3.y);
            float r3 = w0 * bfhi(s0.y) + w1 * bfhi(s1.y) + w2 * bfhi(s2.y) + w3 * bfhi(s3.y);
            *reinterpret_cast<float4*>(op + h0) = make_float4(r0, r1, r2, r3);
        }
    }
}

extern "C" void kernel_launch(void* const* d_in, const int* in_sizes, int n_in,
                              void* d_out, int out_size) {
    const float* x     = (const float*)d_in[0];   // [T, 4*4096] fp32
    const float* fn    = (const float*)d_in[1];   // [4, 16384]  fp32
    const float* scale = (const float*)d_in[2];   // [1]
    const float* base  = (const float*)d_in[3];   // [4]
    float* out = (float*)d_out;                   // [T, 4096] fp32

    const int T = in_sizes[0] / MH;               // 8192
    hchead_kernel<<<T / TOK, NT>>>(x, fn, scale, base, out);
}

// round 5
// speedup vs baseline: 1.2941x; 1.2941x over previous
#include <cuda_runtime.h>
#include <cuda_bf16.h>

#define HID 4096
#define MH 16384             // 4 * HIDDEN
#define TOK 4
#define NT 1024
#define NWARP (NT / 32)      // 32
#define NK (MH / 4 / NT)     // 4 float4-iterations per token
// smem: 4 tokens of bf16 x (128 KB) + reduction scratch + weights
#define SMEM_BYTES (TOK * MH * 2 + (NWARP * 20 + 16) * 4)

__device__ __forceinline__ float bflo(unsigned u) {   // low bf16 -> f32
    return __uint_as_float(u << 16);
}
__device__ __forceinline__ float bfhi(unsigned u) {   // high bf16 -> f32
    return __uint_as_float(u & 0xFFFF0000u);
}

__global__ __launch_bounds__(NT, 1) void hchead_kernel(
    const float* __restrict__ x,
    const float* __restrict__ fn,
    const float* __restrict__ scale,
    const float* __restrict__ base,
    float* __restrict__ out)
{
    extern __shared__ __align__(16) unsigned char smem[];
    __nv_bfloat16* xs = reinterpret_cast<__nv_bfloat16*>(smem);
    float* red = reinterpret_cast<float*>(smem + TOK * MH * 2);
    float* wsh = red + NWARP * 20;

    const int tid  = threadIdx.x;
    const int warp = tid >> 5, lane = tid & 31;
    const size_t tok0 = (size_t)blockIdx.x * TOK;

    const float4* x4  = reinterpret_cast<const float4*>(x);
    const float4* fn4 = reinterpret_cast<const float4*>(fn);

    // acc: t*5+0 = sum(x^2), t*5+1+m = dot with fn[m]
    float acc[20];
#pragma unroll
    for (int i = 0; i < 20; i++) acc[i] = 0.f;

    // ------- Phase 1: load x, bf16-round, stash in smem, accumulate -------
#pragma unroll
    for (int k = 0; k < NK; k++) {          // 4 iterations
        const int f = tid + k * NT;         // float4 index (j = 4f)
        const float4 g0 = fn4[0 * (MH / 4) + f];
        const float4 g1 = fn4[1 * (MH / 4) + f];
        const float4 g2 = fn4[2 * (MH / 4) + f];
        const float4 g3 = fn4[3 * (MH / 4) + f];
        // issue all 4 token loads up front for MLP
        float4 v0 = x4[(tok0 + 0) * (MH / 4) + f];
        float4 v1 = x4[(tok0 + 1) * (MH / 4) + f];
        float4 v2 = x4[(tok0 + 2) * (MH / 4) + f];
        float4 v3 = x4[(tok0 + 3) * (MH / 4) + f];
#pragma unroll
        for (int t = 0; t < TOK; t++) {
            const float4 v = (t == 0) ? v0 : (t == 1) ? v1 : (t == 2) ? v2 : v3;
            __nv_bfloat162 b0 = __floats2bfloat162_rn(v.x, v.y);
            __nv_bfloat162 b1 = __floats2bfloat162_rn(v.z, v.w);
            uint2 st;
            st.x = *reinterpret_cast<unsigned*>(&b0);
            st.y = *reinterpret_cast<unsigned*>(&b1);
            reinterpret_cast<uint2*>(xs + t * MH)[f] = st;
            const float x0 = bflo(st.x), x1 = bfhi(st.x);
            const float x2 = bflo(st.y), x3 = bfhi(st.y);
            acc[t * 5 + 0] += x0 * x0 + x1 * x1 + x2 * x2 + x3 * x3;
            acc[t * 5 + 1] += x0 * g0.x + x1 * g0.y + x2 * g0.z + x3 * g0.w;
            acc[t * 5 + 2] += x0 * g1.x + x1 * g1.y + x2 * g1.z + x3 * g1.w;
            acc[t * 5 + 3] += x0 * g2.x + x1 * g2.y + x2 * g2.z + x3 * g2.w;
            acc[t * 5 + 4] += x0 * g3.x + x1 * g3.y + x2 * g3.z + x3 * g3.w;
        }
    }

    // ------- Block reduction of 20 partials -------
#pragma unroll
    for (int i = 0; i < 20; i++) {
#pragma unroll
        for (int o = 16; o > 0; o >>= 1)
            acc[i] += __shfl_xor_sync(0xffffffffu, acc[i], o);
    }
    if (lane == 0) {
#pragma unroll
        for (int i = 0; i < 20; i++) red[warp * 20 + i] = acc[i];
    }
    __syncthreads();

    if (tid < TOK) {
        const int t = tid;
        float ss = 0.f, d0 = 0.f, d1 = 0.f, d2 = 0.f, d3 = 0.f;
#pragma unroll
        for (int w = 0; w < NWARP; w++) {
            ss += red[w * 20 + t * 5 + 0];
            d0 += red[w * 20 + t * 5 + 1];
            d1 += red[w * 20 + t * 5 + 2];
            d2 += red[w * 20 + t * 5 + 3];
            d3 += red[w * 20 + t * 5 + 4];
        }
        const float inv = 1.0f / sqrtf(ss * (1.0f / MH) + 1e-6f);
        const float s = scale[0];
        const float a0 = s * (d0 * inv) + base[0];
        const float a1 = s * (d1 * inv) + base[1];
        const float a2 = s * (d2 * inv) + base[2];
        const float a3 = s * (d3 * inv) + base[3];
        const float idn = 1.0f / (fabsf(a0) + fabsf(a1) + fabsf(a2) + fabsf(a3) + 1e-6f);
        wsh[t * 4 + 0] = a0 * idn;
        wsh[t * 4 + 1] = a1 * idn;
        wsh[t * 4 + 2] = a2 * idn;
        wsh[t * 4 + 3] = a3 * idn;
    }
    __syncthreads();

    // ------- Phase 2: y[t][h] = sum_m w[t][m] * xf[t][m*HID + h] -------
    // 1024 threads, 4096 h per token -> 4 h (one uint2 per stream) per thread.
#pragma unroll
    for (int t = 0; t < TOK; t++) {
        const float w0 = wsh[t * 4 + 0], w1 = wsh[t * 4 + 1];
        const float w2 = wsh[t * 4 + 2], w3 = wsh[t * 4 + 3];
        const int h0 = tid * 4;
        const __nv_bfloat16* bp = xs + t * MH;
        uint2 s0 = *reinterpret_cast<const uint2*>(bp + 0 * HID + h0);
        uint2 s1 = *reinterpret_cast<const uint2*>(bp + 1 * HID + h0);
        uint2 s2 = *reinterpret_cast<const uint2*>(bp + 2 * HID + h0);
        uint2 s3 = *reinterpret_cast<const uint2*>(bp + 3 * HID + h0);

        float r0 = w0 * bflo(s0.x) + w1 * bflo(s1.x) + w2 * bflo(s2.x) + w3 * bflo(s3.x);
        float r1 = w0 * bfhi(s0.x) + w1 * bfhi(s1.x) + w2 * bfhi(s2.x) + w3 * bfhi(s3.x);
        float r2 = w0 * bflo(s0.y) + w1 * bflo(s1.y) + w2 * bflo(s2.y) + w3 * bflo(s3.y);
        float r3 = w0 * bfhi(s0.y) + w1 * bfhi(s1.y) + w2 * bfhi(s2.y) + w3 * bfhi(s3.y);

        *reinterpret_cast<float4*>(out + (tok0 + t) * HID + h0) =
            make_float4(r0, r1, r2, r3);
    }
}

extern "C" void kernel_launch(void* const* d_in, const int* in_sizes, int n_in,
                              void* d_out, int out_size) {
    const float* x     = (const float*)d_in[0];   // [T, 4*4096] fp32
    const float* fn    = (const float*)d_in[1];   // [4, 16384]  fp32
    const float* scale = (const float*)d_in[2];   // [1]
    const float* base  = (const float*)d_in[3];   // [4]
    float* out = (float*)d_out;                   // [T, 4096] fp32

    const int T = in_sizes[0] / MH;               // 8192

    cudaFuncSetAttribute(hchead_kernel,
                         cudaFuncAttributeMaxDynamicSharedMemorySize, SMEM_BYTES);
    hchead_kernel<<<T / TOK, NT, SMEM_BYTES>>>(x, fn, scale, base, out);
}

// round 6
// speedup vs baseline: 1.3614x; 1.0520x over previous
#include <cuda_runtime.h>
#include <cuda_bf16.h>

#define HID 4096
#define MH 16384             // 4 * HIDDEN
#define TOK 4
#define NT 512
#define NWARP (NT / 32)      // 16
#define NK (MH / 4 / NT)     // 8 float4-iterations per token

__device__ __forceinline__ float bflo(unsigned u) {   // low bf16 -> f32
    return __uint_as_float(u << 16);
}
__device__ __forceinline__ float bfhi(unsigned u) {   // high bf16 -> f32
    return __uint_as_float(u & 0xFFFF0000u);
}
// round fp32 pair -> packed bf16x2 (RN, matches astype(bfloat16))
__device__ __forceinline__ unsigned pack_bf2(float a, float b) {
    __nv_bfloat162 p = __floats2bfloat162_rn(a, b);
    return *reinterpret_cast<unsigned*>(&p);
}

__global__ __launch_bounds__(NT, 2) void hchead_kernel(
    const float* __restrict__ x,
    const float* __restrict__ fn,
    const float* __restrict__ scale,
    const float* __restrict__ base,
    float* __restrict__ out)
{
    __shared__ float red[NWARP * 20];
    __shared__ float wsh[TOK * 4];

    const int tid  = threadIdx.x;
    const int warp = tid >> 5, lane = tid & 31;
    const size_t tok0 = (size_t)blockIdx.x * TOK;

    const float4* x4  = reinterpret_cast<const float4*>(x);
    const float4* fn4 = reinterpret_cast<const float4*>(fn);

    // acc: t*5+0 = sum(x^2), t*5+1+m = dot with fn[m]
    float acc[20];
#pragma unroll
    for (int i = 0; i < 20; i++) acc[i] = 0.f;

    // ------- Phase 1: stream x (DRAM) + fn (L2), accumulate sums -------
#pragma unroll
    for (int k = 0; k < NK; k++) {          // 8 iterations
        const int f = tid + k * NT;         // float4 index (j = 4f)
        const float4 g0 = fn4[0 * (MH / 4) + f];
        const float4 g1 = fn4[1 * (MH / 4) + f];
        const float4 g2 = fn4[2 * (MH / 4) + f];
        const float4 g3 = fn4[3 * (MH / 4) + f];
        float4 v0 = x4[(tok0 + 0) * (MH / 4) + f];
        float4 v1 = x4[(tok0 + 1) * (MH / 4) + f];
        float4 v2 = x4[(tok0 + 2) * (MH / 4) + f];
        float4 v3 = x4[(tok0 + 3) * (MH / 4) + f];
#pragma unroll
        for (int t = 0; t < TOK; t++) {
            const float4 v = (t == 0) ? v0 : (t == 1) ? v1 : (t == 2) ? v2 : v3;
            const unsigned p0 = pack_bf2(v.x, v.y);
            const unsigned p1 = pack_bf2(v.z, v.w);
            const float x0 = bflo(p0), x1 = bfhi(p0);
            const float x2 = bflo(p1), x3 = bfhi(p1);
            acc[t * 5 + 0] += x0 * x0 + x1 * x1 + x2 * x2 + x3 * x3;
            acc[t * 5 + 1] += x0 * g0.x + x1 * g0.y + x2 * g0.z + x3 * g0.w;
            acc[t * 5 + 2] += x0 * g1.x + x1 * g1.y + x2 * g1.z + x3 * g1.w;
            acc[t * 5 + 3] += x0 * g2.x + x1 * g2.y + x2 * g2.z + x3 * g2.w;
            acc[t * 5 + 4] += x0 * g3.x + x1 * g3.y + x2 * g3.z + x3 * g3.w;
        }
    }

    // ------- Block reduction of 20 partials -------
#pragma unroll
    for (int i = 0; i < 20; i++) {
#pragma unroll
        for (int o = 16; o > 0; o >>= 1)
            acc[i] += __shfl_xor_sync(0xffffffffu, acc[i], o);
    }
    if (lane == 0) {
#pragma unroll
        for (int i = 0; i < 20; i++) red[warp * 20 + i] = acc[i];
    }
    __syncthreads();

    if (tid < TOK) {
        const int t = tid;
        float ss = 0.f, d0 = 0.f, d1 = 0.f, d2 = 0.f, d3 = 0.f;
#pragma unroll
        for (int w = 0; w < NWARP; w++) {
            ss += red[w * 20 + t * 5 + 0];
            d0 += red[w * 20 + t * 5 + 1];
            d1 += red[w * 20 + t * 5 + 2];
            d2 += red[w * 20 + t * 5 + 3];
            d3 += red[w * 20 + t * 5 + 4];
        }
        const float inv = 1.0f / sqrtf(ss * (1.0f / MH) + 1e-6f);
        const float s = scale[0];
        const float a0 = s * (d0 * inv) + base[0];
        const float a1 = s * (d1 * inv) + base[1];
        const float a2 = s * (d2 * inv) + base[2];
        const float a3 = s * (d3 * inv) + base[3];
        const float idn = 1.0f / (fabsf(a0) + fabsf(a1) + fabsf(a2) + fabsf(a3) + 1e-6f);
        wsh[t * 4 + 0] = a0 * idn;
        wsh[t * 4 + 1] = a1 * idn;
        wsh[t * 4 + 2] = a2 * idn;
        wsh[t * 4 + 3] = a3 * idn;
    }
    __syncthreads();

    // ------- Phase 2: re-read x from L2, re-round, combine, store -------
    // Each thread: 8 h-positions per token (2 float4 outputs).
#pragma unroll
    for (int t = 0; t < TOK; t++) {
        const float w0 = wsh[t * 4 + 0], w1 = wsh[t * 4 + 1];
        const float w2 = wsh[t * 4 + 2], w3 = wsh[t * 4 + 3];
        const float4* xp = x4 + (tok0 + t) * (MH / 4);
        const int h4 = tid * 2;             // float4 index into hidden dim
        // 8 independent loads (L2 hits)
        float4 a0 = xp[0 * (HID / 4) + h4 + 0];
        float4 a1 = xp[0 * (HID / 4) + h4 + 1];
        float4 b0 = xp[1 * (HID / 4) + h4 + 0];
        float4 b1 = xp[1 * (HID / 4) + h4 + 1];
        float4 c0 = xp[2 * (HID / 4) + h4 + 0];
        float4 c1 = xp[2 * (HID / 4) + h4 + 1];
        float4 d0 = xp[3 * (HID / 4) + h4 + 0];
        float4 d1 = xp[3 * (HID / 4) + h4 + 1];

        float r[8];
        {
            unsigned pa0 = pack_bf2(a0.x, a0.y), pa1 = pack_bf2(a0.z, a0.w);
            unsigned pa2 = pack_bf2(a1.x, a1.y), pa3 = pack_bf2(a1.z, a1.w);
            r[0] = w0 * bflo(pa0); r[1] = w0 * bfhi(pa0);
            r[2] = w0 * bflo(pa1); r[3] = w0 * bfhi(pa1);
            r[4] = w0 * bflo(pa2); r[5] = w0 * bfhi(pa2);
            r[6] = w0 * bflo(pa3); r[7] = w0 * bfhi(pa3);
        }
        {
            unsigned pb0 = pack_bf2(b0.x, b0.y), pb1 = pack_bf2(b0.z, b0.w);
            unsigned pb2 = pack_bf2(b1.x, b1.y), pb3 = pack_bf2(b1.z, b1.w);
            r[0] += w1 * bflo(pb0); r[1] += w1 * bfhi(pb0);
            r[2] += w1 * bflo(pb1); r[3] += w1 * bfhi(pb1);
            r[4] += w1 * bflo(pb2); r[5] += w1 * bfhi(pb2);
            r[6] += w1 * bflo(pb3); r[7] += w1 * bfhi(pb3);
        }
        {
            unsigned pc0 = pack_bf2(c0.x, c0.y), pc1 = pack_bf2(c0.z, c0.w);
            unsigned pc2 = pack_bf2(c1.x, c1.y), pc3 = pack_bf2(c1.z, c1.w);
            r[0] += w2 * bflo(pc0); r[1] += w2 * bfhi(pc0);
            r[2] += w2 * bflo(pc1); r[3] += w2 * bfhi(pc1);
            r[4] += w2 * bflo(pc2); r[5] += w2 * bfhi(pc2);
            r[6] += w2 * bflo(pc3); r[7] += w2 * bfhi(pc3);
        }
        {
            unsigned pd0 = pack_bf2(d0.x, d0.y), pd1 = pack_bf2(d0.z, d0.w);
            unsigned pd2 = pack_bf2(d1.x, d1.y), pd3 = pack_bf2(d1.z, d1.w);
            r[0] += w3 * bflo(pd0); r[1] += w3 * bfhi(pd0);
            r[2] += w3 * bflo(pd1); r[3] += w3 * bfhi(pd1);
            r[4] += w3 * bflo(pd2); r[5] += w3 * bfhi(pd2);
            r[6] += w3 * bflo(pd3); r[7] += w3 * bfhi(pd3);
        }

        float4* op = reinterpret_cast<float4*>(out + (tok0 + t) * HID) + h4;
        op[0] = make_float4(r[0], r[1], r[2], r[3]);
        op[1] = make_float4(r[4], r[5], r[6], r[7]);
    }
}

extern "C" void kernel_launch(void* const* d_in, const int* in_sizes, int n_in,
                              void* d_out, int out_size) {
    const float* x     = (const float*)d_in[0];   // [T, 4*4096] fp32
    const float* fn    = (const float*)d_in[1];   // [4, 16384]  fp32
    const float* scale = (const float*)d_in[2];   // [1]
    const float* base  = (const float*)d_in[3];   // [4]
    float* out = (float*)d_out;                   // [T, 4096] fp32

    const int T = in_sizes[0] / MH;               // 8192
    hchead_kernel<<<T / TOK, NT>>>(x, fn, scale, base, out);
}